// round 3
// baseline (speedup 1.0000x reference)
#include <cuda_runtime.h>
#include <cstdint>

// ---------------------------------------------------------------------------
// CrossAttention: out = softmax((X Wq)(Y Wk)^T / sqrt(d)) (Y Wv) @ Wo + bo
// B=4, Sd=Se=2048, E=1024, H=16, d=64.  All fp32 this round (correctness
// baseline; precision headroom measurement for tf32/tcgen05 next rounds).
// ---------------------------------------------------------------------------

#define EMBED 1024
#define HEADS 16
#define HDIM  64
#define BATCH 4
#define SEQ   2048
#define MTOT  (BATCH * SEQ)   // 8192 rows for all projection GEMMs

// Scratch: __device__ globals (no allocation allowed anywhere).
__device__ float g_Q[MTOT * EMBED];
__device__ float g_K[MTOT * EMBED];
__device__ float g_V[MTOT * EMBED];
__device__ float g_O[MTOT * EMBED];

// ---------------------------------------------------------------------------
// SGEMM: C[M,N] = A[M,K] @ W[K,N] (+ bias[N]).  128x128 block tile, BK=8,
// 256 threads, 8x8 per-thread microtile, LDS.128 operand reads.
// M,N,K all multiples of 128/8 here (no edge guards needed).
// ---------------------------------------------------------------------------
__global__ __launch_bounds__(256)
void sgemm128(const float* __restrict__ A, const float* __restrict__ W,
              const float* __restrict__ bias, float* __restrict__ C,
              int M, int N, int K)
{
    __shared__ float As[8][128];   // transposed A tile: As[k][m]
    __shared__ float Bs[8][128];   // Bs[k][n]

    const int tid  = threadIdx.x;
    const int ty   = tid >> 4;        // 0..15  (row group)
    const int tx   = tid & 15;        // 0..15  (col group)
    const int row0 = blockIdx.y * 128;
    const int col0 = blockIdx.x * 128;

    const int arow = tid >> 1;        // 0..127
    const int acol = (tid & 1) * 4;   // 0 or 4
    const int brow = tid >> 5;        // 0..7
    const int bcol = (tid & 31) * 4;  // 0..124

    const float* Aptr = A + (size_t)(row0 + arow) * K + acol;
    const float* Wptr = W + (size_t)brow * N + col0 + bcol;

    float acc[8][8];
#pragma unroll
    for (int m = 0; m < 8; ++m)
#pragma unroll
        for (int n = 0; n < 8; ++n) acc[m][n] = 0.f;

    for (int kt = 0; kt < K; kt += 8) {
        // Global loads issued before the barrier: overlap with prior compute.
        float4 av = *(const float4*)(Aptr + kt);
        float4 wv = *(const float4*)(Wptr + (size_t)kt * N);
        __syncthreads();   // previous compute done reading smem
        As[acol + 0][arow] = av.x;
        As[acol + 1][arow] = av.y;
        As[acol + 2][arow] = av.z;
        As[acol + 3][arow] = av.w;
        *(float4*)&Bs[brow][bcol] = wv;
        __syncthreads();
#pragma unroll
        for (int k = 0; k < 8; ++k) {
            float4 a0 = *(const float4*)&As[k][ty * 8];
            float4 a1 = *(const float4*)&As[k][ty * 8 + 4];
            float4 b0 = *(const float4*)&Bs[k][tx * 8];
            float4 b1 = *(const float4*)&Bs[k][tx * 8 + 4];
            float a[8] = {a0.x, a0.y, a0.z, a0.w, a1.x, a1.y, a1.z, a1.w};
            float b[8] = {b0.x, b0.y, b0.z, b0.w, b1.x, b1.y, b1.z, b1.w};
#pragma unroll
            for (int m = 0; m < 8; ++m)
#pragma unroll
                for (int n = 0; n < 8; ++n)
                    acc[m][n] = fmaf(a[m], b[n], acc[m][n]);
        }
    }

    float bvals[8];
#pragma unroll
    for (int n = 0; n < 8; ++n)
        bvals[n] = bias ? bias[col0 + tx * 8 + n] : 0.f;

#pragma unroll
    for (int m = 0; m < 8; ++m) {
        float* crow = C + (size_t)(row0 + ty * 8 + m) * N + col0 + tx * 8;
        float4 o0 = make_float4(acc[m][0] + bvals[0], acc[m][1] + bvals[1],
                                acc[m][2] + bvals[2], acc[m][3] + bvals[3]);
        float4 o1 = make_float4(acc[m][4] + bvals[4], acc[m][5] + bvals[5],
                                acc[m][6] + bvals[6], acc[m][7] + bvals[7]);
        *(float4*)crow       = o0;
        *(float4*)(crow + 4) = o1;
    }
}

// ---------------------------------------------------------------------------
// Flash-attention (fp32, online softmax).  One block = one (b,h) pair and a
// 128-row Q tile; loop over Se in 64-row KV chunks.
// 256 threads; S microtile 8x4 per thread; O accumulator 8x4 per thread.
// Q/K/V/O are stored [B*S, E] with head h occupying cols h*64..h*64+63, so
// the attention output lands directly in the layout the final GEMM needs.
// ---------------------------------------------------------------------------
#define BQ   128
#define BKV  64
#define QSTR 65   // +1 pad: ty-row stride not a multiple of 4 -> no bank clash

struct AttnSmem {
    float Q[BQ][QSTR];
    float K[BKV][QSTR];
    float V[BKV][QSTR];
    float P[BQ][QSTR];
    float M[BQ];
    float L[BQ];
    float Cf[BQ];
};

__global__ __launch_bounds__(256)
void attn_kernel(const float* __restrict__ Qg, const float* __restrict__ Kg,
                 const float* __restrict__ Vg, float* __restrict__ Og)
{
    extern __shared__ char smem_raw[];
    AttnSmem& sm = *reinterpret_cast<AttnSmem*>(smem_raw);

    const int tid   = threadIdx.x;
    const int qtile = blockIdx.x;            // 0..15
    const int bh    = blockIdx.y;            // 0..63
    const int b     = bh / HEADS;
    const int h     = bh - b * HEADS;
    const size_t base = (size_t)b * SEQ * EMBED + (size_t)h * HDIM;
    const int q0 = qtile * BQ;

    // Load Q tile: 128 rows x 64 cols (each row 256B contiguous in gmem).
#pragma unroll
    for (int t = 0; t < 8; ++t) {
        int i  = tid + t * 256;              // 0..2047
        int r  = i >> 4;
        int c4 = (i & 15) * 4;
        float4 v = *(const float4*)&Qg[base + (size_t)(q0 + r) * EMBED + c4];
        sm.Q[r][c4 + 0] = v.x;
        sm.Q[r][c4 + 1] = v.y;
        sm.Q[r][c4 + 2] = v.z;
        sm.Q[r][c4 + 3] = v.w;
    }
    if (tid < BQ) { sm.M[tid] = -3.0e38f; sm.L[tid] = 0.f; }

    const int ty = tid >> 4;   // 0..15 -> S/O rows ty*8..ty*8+7
    const int tx = tid & 15;   // 0..15 -> S cols tx*4..tx*4+3 / O dims tx*4..

    float Oacc[8][4];
#pragma unroll
    for (int m = 0; m < 8; ++m)
#pragma unroll
        for (int j = 0; j < 4; ++j) Oacc[m][j] = 0.f;

    for (int kv0 = 0; kv0 < SEQ; kv0 += BKV) {
        __syncthreads();  // prior iteration done with K/V/P (also covers Q init)

        // Load K,V chunk: 64 rows x 64 cols each.
#pragma unroll
        for (int t = 0; t < 4; ++t) {
            int i  = tid + t * 256;          // 0..1023
            int r  = i >> 4;
            int c4 = (i & 15) * 4;
            size_t goff = base + (size_t)(kv0 + r) * EMBED + c4;
            float4 kv = *(const float4*)&Kg[goff];
            float4 vv = *(const float4*)&Vg[goff];
            sm.K[r][c4 + 0] = kv.x; sm.K[r][c4 + 1] = kv.y;
            sm.K[r][c4 + 2] = kv.z; sm.K[r][c4 + 3] = kv.w;
            sm.V[r][c4 + 0] = vv.x; sm.V[r][c4 + 1] = vv.y;
            sm.V[r][c4 + 2] = vv.z; sm.V[r][c4 + 3] = vv.w;
        }
        __syncthreads();

        // S = (Q K^T) * 1/sqrt(d)
        float s[8][4];
#pragma unroll
        for (int m = 0; m < 8; ++m)
#pragma unroll
            for (int j = 0; j < 4; ++j) s[m][j] = 0.f;

#pragma unroll 8
        for (int k = 0; k < HDIM; ++k) {
            float a[8], bb[4];
#pragma unroll
            for (int m = 0; m < 8; ++m) a[m] = sm.Q[ty * 8 + m][k];
#pragma unroll
            for (int j = 0; j < 4; ++j) bb[j] = sm.K[tx * 4 + j][k];
#pragma unroll
            for (int m = 0; m < 8; ++m)
#pragma unroll
                for (int j = 0; j < 4; ++j)
                    s[m][j] = fmaf(a[m], bb[j], s[m][j]);
        }
#pragma unroll
        for (int m = 0; m < 8; ++m)
#pragma unroll
            for (int j = 0; j < 4; ++j)
                sm.P[ty * 8 + m][tx * 4 + j] = s[m][j] * 0.125f;
        __syncthreads();

        // Online softmax: 2 threads per row, 32 cols each.
        {
            int row  = tid >> 1;
            int half = tid & 1;
            float* prow = &sm.P[row][half * 32];
            float mx = -3.0e38f;
#pragma unroll
            for (int c = 0; c < 32; ++c) mx = fmaxf(mx, prow[c]);
            mx = fmaxf(mx, __shfl_xor_sync(0xffffffffu, mx, 1));
            float mo   = sm.M[row];
            float mn   = fmaxf(mo, mx);
            float corr = __expf(mo - mn);
            float ls = 0.f;
#pragma unroll
            for (int c = 0; c < 32; ++c) {
                float p = __expf(prow[c] - mn);
                prow[c] = p;
                ls += p;
            }
            ls += __shfl_xor_sync(0xffffffffu, ls, 1);
            if (half == 0) {
                sm.M[row]  = mn;
                sm.L[row]  = sm.L[row] * corr + ls;
                sm.Cf[row] = corr;
            }
        }
        __syncthreads();

        // O = O * corr + P @ V
        float cr[8];
#pragma unroll
        for (int m = 0; m < 8; ++m) cr[m] = sm.Cf[ty * 8 + m];
#pragma unroll
        for (int m = 0; m < 8; ++m)
#pragma unroll
            for (int j = 0; j < 4; ++j) Oacc[m][j] *= cr[m];

#pragma unroll 8
        for (int c = 0; c < BKV; ++c) {
            float p[8], v[4];
#pragma unroll
            for (int m = 0; m < 8; ++m) p[m] = sm.P[ty * 8 + m][c];
#pragma unroll
            for (int j = 0; j < 4; ++j) v[j] = sm.V[c][tx * 4 + j];
#pragma unroll
            for (int m = 0; m < 8; ++m)
#pragma unroll
                for (int j = 0; j < 4; ++j)
                    Oacc[m][j] = fmaf(p[m], v[j], Oacc[m][j]);
        }
    }

    // Normalize and store (layout matches the final GEMM's A operand).
#pragma unroll
    for (int m = 0; m < 8; ++m) {
        int r = ty * 8 + m;
        float inv = 1.0f / sm.L[r];
        float4 o = make_float4(Oacc[m][0] * inv, Oacc[m][1] * inv,
                               Oacc[m][2] * inv, Oacc[m][3] * inv);
        *(float4*)&Og[base + (size_t)(q0 + r) * EMBED + tx * 4] = o;
    }
}

// ---------------------------------------------------------------------------
// Launch: 3 projection GEMMs -> flash attention -> output GEMM (+bias).
// All plain kernel launches on the capture stream; no allocs, no syncs.
// ---------------------------------------------------------------------------
extern "C" void kernel_launch(void* const* d_in, const int* in_sizes, int n_in,
                              void* d_out, int out_size)
{
    const float* dec = (const float*)d_in[0];   // [4,2048,1024]
    const float* enc = (const float*)d_in[1];   // [4,2048,1024]
    const float* Wq  = (const float*)d_in[2];   // [1024,1024]
    const float* Wk  = (const float*)d_in[3];
    const float* Wv  = (const float*)d_in[4];
    const float* Wo  = (const float*)d_in[5];
    const float* bo  = (const float*)d_in[6];   // [1024]
    float* out = (float*)d_out;                 // [4,2048,1024]

    float *Qp, *Kp, *Vp, *Op;
    cudaGetSymbolAddress((void**)&Qp, g_Q);
    cudaGetSymbolAddress((void**)&Kp, g_K);
    cudaGetSymbolAddress((void**)&Vp, g_V);
    cudaGetSymbolAddress((void**)&Op, g_O);

    cudaFuncSetAttribute(attn_kernel,
                         cudaFuncAttributeMaxDynamicSharedMemorySize,
                         (int)sizeof(AttnSmem));

    dim3 gemm_grid(EMBED / 128, MTOT / 128);   // (8, 64)

    sgemm128<<<gemm_grid, 256>>>(dec, Wq, nullptr, Qp, MTOT, EMBED, EMBED);
    sgemm128<<<gemm_grid, 256>>>(enc, Wk, nullptr, Kp, MTOT, EMBED, EMBED);
    sgemm128<<<gemm_grid, 256>>>(enc, Wv, nullptr, Vp, MTOT, EMBED, EMBED);

    attn_kernel<<<dim3(SEQ / BQ, BATCH * HEADS), 256, sizeof(AttnSmem)>>>(
        Qp, Kp, Vp, Op);

    sgemm128<<<gemm_grid, 256>>>(Op, Wo, bo, out, MTOT, EMBED, EMBED);
}